// round 14
// baseline (speedup 1.0000x reference)
#include <cuda_runtime.h>
#include <cuda_bf16.h>
#include <stdint.h>
#include <math.h>

// ---------------------------------------------------------------------------
// Problem constants
// ---------------------------------------------------------------------------
#define BB 2
#define SS 512
#define HH 1024
#define NHH 16
#define HD 64
#define TT (BB*SS)          // 1024 tokens
#define EE 32               // experts
#define DD 8                // devices
#define KK 6                // top-k experts
#define KDD 3               // top devices
#define EPD (EE/DD)         // 4 experts per device
#define INTER 1536
#define GU (2*INTER)        // 3072
#define EPSF 1e-5f
#define TOTSEL (TT*KK)      // 6144

// ---------------------------------------------------------------------------
// Scratch (static device globals; accessed ONLY by device-code symbol refs)
// ---------------------------------------------------------------------------
__device__ float g_qkv   [TT * 3 * HH];
__device__ float g_attn  [TT * HH];
__device__ float g_attno [TT * HH];
__device__ float g_h1    [TT * HH];
__device__ float g_gu    [TOTSEL * GU];
__device__ float g_act   [TOTSEL * INTER];
__device__ float g_shared[2 * TT * HH];     // two z-halves, summed in k_final
__device__ float g_routed[TT * HH];

__device__ int   g_idx   [TT * KK];
__device__ float g_w     [TT * KK];
__device__ int   g_cnt   [EE];
__device__ int   g_off   [EE];
__device__ int   g_cur   [EE];
__device__ int   g_tok   [TOTSEL];
__device__ float g_wt    [TOTSEL];
__device__ float g_probsum[EE];
__device__ float g_devhit [DD];

#define BUF_QKV    0
#define BUF_ATTN   1
#define BUF_ATTNO  2
#define BUF_H1     3
#define BUF_GU     4
#define BUF_ACT    5
#define BUF_SHARED 6
__device__ __forceinline__ float* devbuf(int id) {
    switch (id) {
        case BUF_QKV:    return g_qkv;
        case BUF_ATTN:   return g_attn;
        case BUF_ATTNO:  return g_attno;
        case BUF_H1:     return g_h1;
        case BUF_GU:     return g_gu;
        case BUF_ACT:    return g_act;
        case BUF_SHARED: return g_shared;
        default:         return g_routed;
    }
}

// ---------------------------------------------------------------------------
// PTX helpers (base ISA: ldmatrix + mma.sync)
// ---------------------------------------------------------------------------
__device__ __forceinline__ uint32_t smem_u32(const void* p) {
    uint32_t a;
    asm("{ .reg .u64 t; cvta.to.shared.u64 t, %1; cvt.u32.u64 %0, t; }" : "=r"(a) : "l"(p));
    return a;
}
__device__ __forceinline__ void ldsm_x4(uint32_t& r0, uint32_t& r1, uint32_t& r2, uint32_t& r3,
                                        uint32_t addr) {
    asm volatile("ldmatrix.sync.aligned.m8n8.x4.shared.b16 {%0,%1,%2,%3}, [%4];"
                 : "=r"(r0), "=r"(r1), "=r"(r2), "=r"(r3) : "r"(addr));
}
__device__ __forceinline__ void ldsm_x4_t(uint32_t& r0, uint32_t& r1, uint32_t& r2, uint32_t& r3,
                                          uint32_t addr) {
    asm volatile("ldmatrix.sync.aligned.m8n8.x4.trans.shared.b16 {%0,%1,%2,%3}, [%4];"
                 : "=r"(r0), "=r"(r1), "=r"(r2), "=r"(r3) : "r"(addr));
}
__device__ __forceinline__ void mma_bf16(float* c, const uint32_t* a, const uint32_t* b) {
    asm volatile("mma.sync.aligned.m16n8k16.row.col.f32.bf16.bf16.f32 "
                 "{%0,%1,%2,%3}, {%4,%5,%6,%7}, {%8,%9}, {%0,%1,%2,%3};"
                 : "+f"(c[0]), "+f"(c[1]), "+f"(c[2]), "+f"(c[3])
                 : "r"(a[0]), "r"(a[1]), "r"(a[2]), "r"(a[3]), "r"(b[0]), "r"(b[1]));
}
// pack (lo_elem, hi_elem) -> bf16x2; first PTX source goes to the HIGH half
__device__ __forceinline__ uint32_t pk_bf16x2(float lo, float hi) {
    uint32_t r;
    asm("cvt.rn.bf16x2.f32 %0, %1, %2;" : "=r"(r) : "f"(hi), "f"(lo));
    return r;
}
__device__ __forceinline__ float bf16_round(float x) {
    return __bfloat162float(__float2bfloat16(x));
}

// ---------------------------------------------------------------------------
// bf16-split tensor-core GEMM:  C[M,N] = A[M,K] @ W[K,N]  (fp32 in/out)
//   A@B ~= Ahi*Bhi + Alo*Bhi + Ahi*Blo  (fp32 accumulate, err ~2^-18)
// MODE 0: plain (z-batched via AzRows/CzRows row offsets)
// MODE 1: gather (rows via g_tok)  | MODE 2: weighted scatter
// Tile 64x128x32, 256 threads (8 warps as 4x2), DOUBLE-BUFFERED smem,
// one __syncthreads per k-iter; LDG of next tile issued before MMA phase.
// ---------------------------------------------------------------------------
#define BM 64
#define BN 128
#define BK 32
#define SA (BK + 8)         // 40 bf16 per A row
#define SB (BN + 8)         // 136 bf16 per B row
#define A_ELE (BM * SA)     // 2560
#define B_ELE (BK * SB)     // 4352
#define GSMEM ((4 * A_ELE + 4 * B_ELE) * 2)   // 55296 bytes

template<int MODE>
__global__ __launch_bounds__(256, 1)
void mma_gemm(const float* __restrict__ Aext, int Aid, int Cid,
              const float* __restrict__ W, long long Wstride,
              int K, int N, long long AzRows, long long CzRows)
{
    extern __shared__ __align__(16) char smraw[];
    __nv_bfloat16* smb = (__nv_bfloat16*)smraw;
    // stage layout (bf16 units)
    __nv_bfloat16* AH[2] = { smb,               smb + A_ELE };
    __nv_bfloat16* AL[2] = { smb + 2*A_ELE,     smb + 3*A_ELE };
    __nv_bfloat16* BH[2] = { smb + 4*A_ELE,             smb + 4*A_ELE + B_ELE };
    __nv_bfloat16* BL[2] = { smb + 4*A_ELE + 2*B_ELE,   smb + 4*A_ELE + 3*B_ELE };
    const uint32_t uAH[2] = { smem_u32(AH[0]), smem_u32(AH[1]) };
    const uint32_t uAL[2] = { smem_u32(AL[0]), smem_u32(AL[1]) };
    const uint32_t uBH[2] = { smem_u32(BH[0]), smem_u32(BH[1]) };
    const uint32_t uBL[2] = { smem_u32(BL[0]), smem_u32(BL[1]) };

    const int tid  = threadIdx.x;
    const int lane = tid & 31;
    const int warp = tid >> 5;
    const int wm = warp >> 1;          // 0..3
    const int wn = warp & 1;           // 0..1
    const int m0 = blockIdx.y * BM;
    const int n0 = blockIdx.x * BN;
    const int z  = blockIdx.z;

    int cnt = 0, off = 0;
    if (MODE != 0) {
        cnt = g_cnt[z];
        off = g_off[z];
        if (m0 >= cnt) return;
    }
    const float* Wb = W + (size_t)z * (size_t)Wstride;
    const float* Abase = (MODE == 0) ? (Aext ? Aext : devbuf(Aid)) : nullptr;

    // fill coordinates: A = 2 float4 chunks, B = 4 float4 chunks per thread
    int arow[2], akc[2], brow[4], bnc[4];
    const float* aptr[2];
    #pragma unroll
    for (int i = 0; i < 2; ++i) {
        int ca = tid + i * 256;
        arow[i] = ca >> 3;
        akc[i]  = (ca & 7) * 4;
        int lr = m0 + arow[i];
        if (MODE == 0)      aptr[i] = Abase + (size_t)(z * AzRows + lr) * (size_t)K;
        else if (MODE == 1) aptr[i] = (lr < cnt) ? g_h1 + (size_t)g_tok[off + lr] * HH : nullptr;
        else                aptr[i] = (lr < cnt) ? g_act + (size_t)(off + lr) * (size_t)K : nullptr;
    }
    #pragma unroll
    for (int i = 0; i < 4; ++i) {
        int ca = tid + i * 256;
        brow[i] = ca >> 5;
        bnc[i]  = (ca & 31) * 4;
    }

    float acc[8][4];
    #pragma unroll
    for (int j = 0; j < 8; ++j)
        #pragma unroll
        for (int c = 0; c < 4; ++c) acc[j][c] = 0.f;

    float4 av[2], bv[4];
    const int niter = K / BK;

    // ---- prologue: load+convert+store tile 0 ----
    #pragma unroll
    for (int i = 0; i < 2; ++i)
        av[i] = aptr[i] ? *(const float4*)(aptr[i] + akc[i]) : make_float4(0.f,0.f,0.f,0.f);
    #pragma unroll
    for (int i = 0; i < 4; ++i)
        bv[i] = *(const float4*)(Wb + (size_t)brow[i] * (size_t)N + n0 + bnc[i]);
    #pragma unroll
    for (int i = 0; i < 2; ++i) {
        float hx = bf16_round(av[i].x), hy = bf16_round(av[i].y);
        float hz = bf16_round(av[i].z), hw = bf16_round(av[i].w);
        *(uint2*)&AH[0][arow[i] * SA + akc[i]] =
            make_uint2(pk_bf16x2(av[i].x, av[i].y), pk_bf16x2(av[i].z, av[i].w));
        *(uint2*)&AL[0][arow[i] * SA + akc[i]] =
            make_uint2(pk_bf16x2(av[i].x - hx, av[i].y - hy), pk_bf16x2(av[i].z - hz, av[i].w - hw));
    }
    #pragma unroll
    for (int i = 0; i < 4; ++i) {
        float gx = bf16_round(bv[i].x), gy = bf16_round(bv[i].y);
        float gz = bf16_round(bv[i].z), gw = bf16_round(bv[i].w);
        *(uint2*)&BH[0][brow[i] * SB + bnc[i]] =
            make_uint2(pk_bf16x2(bv[i].x, bv[i].y), pk_bf16x2(bv[i].z, bv[i].w));
        *(uint2*)&BL[0][brow[i] * SB + bnc[i]] =
            make_uint2(pk_bf16x2(bv[i].x - gx, bv[i].y - gy), pk_bf16x2(bv[i].z - gz, bv[i].w - gw));
    }
    __syncthreads();

    for (int it = 0; it < niter; ++it) {
        const int cur = it & 1, nxt = cur ^ 1;
        const bool more = (it + 1 < niter);

        // ---- (a) issue LDGs for next tile (latency hides under MMA) ----
        if (more) {
            const int k0 = (it + 1) * BK;
            #pragma unroll
            for (int i = 0; i < 2; ++i)
                av[i] = aptr[i] ? *(const float4*)(aptr[i] + k0 + akc[i])
                                : make_float4(0.f,0.f,0.f,0.f);
            #pragma unroll
            for (int i = 0; i < 4; ++i)
                bv[i] = *(const float4*)(Wb + (size_t)(k0 + brow[i]) * (size_t)N + n0 + bnc[i]);
        }

        // ---- (b) MMA phase on current stage ----
        #pragma unroll
        for (int s = 0; s < 2; ++s) {
            uint32_t ah[4], al[4], bh[4][4], bl[4][4];
            const int ar = lane & 15;
            const int ac = s * 16 + (lane >> 4) * 8;
            ldsm_x4(ah[0], ah[1], ah[2], ah[3], uAH[cur] + ((wm * 16 + ar) * SA + ac) * 2);
            ldsm_x4(al[0], al[1], al[2], al[3], uAL[cur] + ((wm * 16 + ar) * SA + ac) * 2);
            const int br = s * 16 + (lane & 15);
            #pragma unroll
            for (int g = 0; g < 4; ++g) {
                int bc = wn * 64 + g * 16 + (lane >> 4) * 8;
                ldsm_x4_t(bh[g][0], bh[g][1], bh[g][2], bh[g][3], uBH[cur] + (br * SB + bc) * 2);
                ldsm_x4_t(bl[g][0], bl[g][1], bl[g][2], bl[g][3], uBL[cur] + (br * SB + bc) * 2);
            }
            // three groups of 8 independent MMAs (no RAW chains at pipe head)
            #pragma unroll
            for (int j = 0; j < 8; ++j) mma_bf16(acc[j], ah, &bh[j >> 1][(j & 1) * 2]);
            #pragma unroll
            for (int j = 0; j < 8; ++j) mma_bf16(acc[j], al, &bh[j >> 1][(j & 1) * 2]);
            #pragma unroll
            for (int j = 0; j < 8; ++j) mma_bf16(acc[j], ah, &bl[j >> 1][(j & 1) * 2]);
        }

        // ---- (c) convert + store next stage ----
        if (more) {
            #pragma unroll
            for (int i = 0; i < 2; ++i) {
                float hx = bf16_round(av[i].x), hy = bf16_round(av[i].y);
                float hz = bf16_round(av[i].z), hw = bf16_round(av[i].w);
                *(uint2*)&AH[nxt][arow[i] * SA + akc[i]] =
                    make_uint2(pk_bf16x2(av[i].x, av[i].y), pk_bf16x2(av[i].z, av[i].w));
                *(uint2*)&AL[nxt][arow[i] * SA + akc[i]] =
                    make_uint2(pk_bf16x2(av[i].x - hx, av[i].y - hy),
                               pk_bf16x2(av[i].z - hz, av[i].w - hw));
            }
            #pragma unroll
            for (int i = 0; i < 4; ++i) {
                float gx = bf16_round(bv[i].x), gy = bf16_round(bv[i].y);
                float gz = bf16_round(bv[i].z), gw = bf16_round(bv[i].w);
                *(uint2*)&BH[nxt][brow[i] * SB + bnc[i]] =
                    make_uint2(pk_bf16x2(bv[i].x, bv[i].y), pk_bf16x2(bv[i].z, bv[i].w));
                *(uint2*)&BL[nxt][brow[i] * SB + bnc[i]] =
                    make_uint2(pk_bf16x2(bv[i].x - gx, bv[i].y - gy),
                               pk_bf16x2(bv[i].z - gz, bv[i].w - gw));
            }
        }
        __syncthreads();
    }

    // ---- epilogue ----
    const int gq = lane >> 2;
    const int tq = lane & 3;
    const int rr0 = wm * 16 + gq;
    const int rr1 = rr0 + 8;
    #pragma unroll
    for (int j = 0; j < 8; ++j) {
        const int col = n0 + wn * 64 + j * 8 + tq * 2;
        float d0 = acc[j][0], d1 = acc[j][1], d2 = acc[j][2], d3 = acc[j][3];
        if (MODE == 0) {
            float* C = devbuf(Cid) + (size_t)z * (size_t)CzRows * (size_t)N;
            *(float2*)&C[(size_t)(m0 + rr0) * (size_t)N + col] = make_float2(d0, d1);
            *(float2*)&C[(size_t)(m0 + rr1) * (size_t)N + col] = make_float2(d2, d3);
        } else if (MODE == 1) {
            if (m0 + rr0 < cnt)
                *(float2*)&g_gu[(size_t)(off + m0 + rr0) * (size_t)N + col] = make_float2(d0, d1);
            if (m0 + rr1 < cnt)
                *(float2*)&g_gu[(size_t)(off + m0 + rr1) * (size_t)N + col] = make_float2(d2, d3);
        } else {
            if (m0 + rr0 < cnt) {
                int token = g_tok[off + m0 + rr0];
                float wt  = g_wt[off + m0 + rr0];
                atomicAdd(&g_routed[(size_t)token * HH + col],     wt * d0);
                atomicAdd(&g_routed[(size_t)token * HH + col + 1], wt * d1);
            }
            if (m0 + rr1 < cnt) {
                int token = g_tok[off + m0 + rr1];
                float wt  = g_wt[off + m0 + rr1];
                atomicAdd(&g_routed[(size_t)token * HH + col],     wt * d2);
                atomicAdd(&g_routed[(size_t)token * HH + col + 1], wt * d3);
            }
        }
    }
}

// ---------------------------------------------------------------------------
// Zero-init (graph replays)
// ---------------------------------------------------------------------------
__global__ void k_zero() {
    int i = blockIdx.x * blockDim.x + threadIdx.x;
    if (i < TT * HH) g_routed[i] = 0.f;
    if (i < EE) { g_cnt[i] = 0; g_probsum[i] = 0.f; }
    if (i < DD) g_devhit[i] = 0.f;
}

// ---------------------------------------------------------------------------
// Attention v2 (unchanged from round 13)
// ---------------------------------------------------------------------------
#define AQB 16
#define KTS 65
#define A_KT 0
#define A_QS (64 * KTS)
#define A_QSN (A_QS + AQB * 64)
#define ATT_SMEM ((A_QSN + AQB * SS) * 4)

__global__ void k_attn2()
{
    extern __shared__ float sm[];
    const int tid = threadIdx.x, lane = tid & 31, w = tid >> 5;
    const int q0 = blockIdx.x * AQB;
    const int h = blockIdx.y, b = blockIdx.z;
    const size_t base = (size_t)b * SS * 3 * HH + (size_t)h * HD;
    const int wq = w * 4;

    for (int i = tid; i < AQB * 16; i += 128) {
        int qi = i >> 4, dc = (i & 15) * 4;
        *(float4*)&sm[A_QS + qi * 64 + dc] =
            *(const float4*)(g_qkv + base + (size_t)(q0 + qi) * (3 * HH) + dc);
    }

    for (int t = 0; t < SS / 64; ++t) {
        __syncthreads();
        for (int i = tid; i < 64 * 16; i += 128) {
            int kr = i >> 4, dc = (i & 15) * 4;
            float4 kv = *(const float4*)(g_qkv + base + HH +
                                         (size_t)(t * 64 + kr) * (3 * HH) + dc);
            float* d = &sm[A_KT + kr * KTS + dc];
            d[0] = kv.x; d[1] = kv.y; d[2] = kv.z; d[3] = kv.w;
        }
        __syncthreads();
        float s0[4] = {0,0,0,0}, s1[4] = {0,0,0,0};
        #pragma unroll 4
        for (int d4 = 0; d4 < 16; ++d4) {
            const int d = d4 * 4;
            const float* k0p = &sm[A_KT + lane * KTS + d];
            const float* k1p = &sm[A_KT + (lane + 32) * KTS + d];
            float k00 = k0p[0], k01 = k0p[1], k02 = k0p[2], k03 = k0p[3];
            float k10 = k1p[0], k11 = k1p[1], k12 = k1p[2], k13 = k1p[3];
            #pragma unroll
            for (int j = 0; j < 4; ++j) {
                float4 qv = *(float4*)&sm[A_QS + (wq + j) * 64 + d];
                s0[j] += qv.x * k00 + qv.y * k01 + qv.z * k02 + qv.w * k03;
                s1[j] += qv.x * k10 + qv.y * k11 + qv.z * k12 + qv.w * k13;
            }
        }
        #pragma unroll
        for (int j = 0; j < 4; ++j) {
            sm[A_QSN + (wq + j) * SS + t * 64 + lane]      = s0[j] * 0.125f;
            sm[A_QSN + (wq + j) * SS + t * 64 + lane + 32] = s1[j] * 0.125f;
        }
    }
    __syncthreads();

    float inv[4];
    #pragma unroll
    for (int j = 0; j < 4; ++j) {
        float* row = &sm[A_QSN + (wq + j) * SS];
        float m = -INFINITY;
        for (int i = lane; i < SS; i += 32) m = fmaxf(m, row[i]);
        #pragma unroll
        for (int o = 16; o > 0; o >>= 1) m = fmaxf(m, __shfl_xor_sync(0xffffffffu, m, o));
        float sum = 0.f;
        for (int i = lane; i < SS; i += 32) {
            float p = expf(row[i] - m);
            row[i] = p;
            sum += p;
        }
        #pragma unroll
        for (int o = 16; o > 0; o >>= 1) sum += __shfl_xor_sync(0xffffffffu, sum, o);
        inv[j] = 1.f / sum;
    }

    float2 acc[4] = {{0.f,0.f},{0.f,0.f},{0.f,0.f},{0.f,0.f}};
    for (int t = 0; t < SS / 64; ++t) {
        __syncthreads();
        for (int i = tid; i < 64 * 16; i += 128) {
            int kr = i >> 4, dc = (i & 15) * 4;
            float4 vv = *(const float4*)(g_qkv + base + 2 * HH +
                                         (size_t)(t * 64 + kr) * (3 * HH) + dc);
            float* d = &sm[A_KT + kr * KTS + dc];
            d[0] = vv.x; d[1] = vv.y; d[2] = vv.z; d[3] = vv.w;
        }
        __syncthreads();
        #pragma unroll 4
        for (int kk = 0; kk < 64; ++kk) {
            float vx = sm[A_KT + kk * KTS + lane];
            float vy = sm[A_KT + kk * KTS + lane + 32];
            #pragma unroll
            for (int j = 0; j < 4; ++j) {
                float pp = sm[A_QSN + (wq + j) * SS + t * 64 + kk];
                acc[j].x += pp * vx;
                acc[j].y += pp * vy;
            }
        }
    }

    #pragma unroll
    for (int j = 0; j < 4; ++j) {
        float* o = g_attn + (size_t)(b * SS + q0 + wq + j) * HH + h * HD;
        o[lane]      = acc[j].x * inv[j];
        o[lane + 32] = acc[j].y * inv[j];
    }
}

// ---------------------------------------------------------------------------
// h1 = rmsnorm(x + attno)
// ---------------------------------------------------------------------------
__global__ void k_addrms(const float* __restrict__ x)
{
    __shared__ float ys[HH];
    __shared__ float red[256];
    const int r = blockIdx.x;
    float ss = 0.f;
    for (int i = threadIdx.x; i < HH; i += 256) {
        float v = x[(size_t)r * HH + i] + g_attno[(size_t)r * HH + i];
        ys[i] = v;
        ss += v * v;
    }
    red[threadIdx.x] = ss;
    __syncthreads();
    for (int s = 128; s > 0; s >>= 1) {
        if (threadIdx.x < s) red[threadIdx.x] += red[threadIdx.x + s];
        __syncthreads();
    }
    float scale = rsqrtf(red[0] / (float)HH + EPSF);
    for (int i = threadIdx.x; i < HH; i += 256)
        g_h1[(size_t)r * HH + i] = ys[i] * scale;
}

// ---------------------------------------------------------------------------
// SwiGLU activation
// ---------------------------------------------------------------------------
__global__ void k_act(int rows)
{
    const long long n = (long long)rows * INTER;
    for (long long i = (long long)blockIdx.x * blockDim.x + threadIdx.x;
         i < n; i += (long long)gridDim.x * blockDim.x) {
        long long r = i / INTER;
        long long j = i % INTER;
        float g = g_gu[r * GU + j];
        float u = g_gu[r * GU + INTER + j];
        float s = g / (1.f + expf(-g));
        g_act[i] = s * u;
    }
}

// ---------------------------------------------------------------------------
// Router: one warp per token.
// ---------------------------------------------------------------------------
__global__ void k_route(const float* __restrict__ Wr)
{
    __shared__ float xr[HH];
    __shared__ float logit_s[EE];
    __shared__ float probs[EE];
    const int t = blockIdx.x;
    const int lane = threadIdx.x;

    for (int i = lane; i < HH; i += 32) xr[i] = g_h1[(size_t)t * HH + i];
    __syncwarp();
    float acc = 0.f;
    for (int hh = 0; hh < HH; ++hh)
        acc = fmaf(xr[hh], Wr[(size_t)hh * EE + lane], acc);
    logit_s[lane] = acc;
    __syncwarp();

    if (lane == 0) {
        float m = -INFINITY;
        for (int e = 0; e < EE; ++e) m = fmaxf(m, logit_s[e]);
        float s = 0.f;
        for (int e = 0; e < EE; ++e) { float p = expf(logit_s[e] - m); probs[e] = p; s += p; }
        float inv = 1.f / s;
        for (int e = 0; e < EE; ++e) probs[e] *= inv;

        float dev[DD];
        for (int d = 0; d < DD; ++d)
            dev[d] = probs[4*d] + probs[4*d+1] + probs[4*d+2] + probs[4*d+3];
        bool devsel[DD];
        for (int d = 0; d < DD; ++d) devsel[d] = false;
        for (int rr = 0; rr < KDD; ++rr) {
            float best = -INFINITY; int bi = -1;
            for (int d = 0; d < DD; ++d)
                if (!devsel[d] && dev[d] > best) { best = dev[d]; bi = d; }
            devsel[bi] = true;
        }
        int idx6[KK]; float w6[KK];
        bool taken[EE];
        for (int e = 0; e < EE; ++e) taken[e] = false;
        for (int rr = 0; rr < KK; ++rr) {
            float best = -INFINITY; int bi = -1;
            for (int e = 0; e < EE; ++e)
                if (devsel[e >> 2] && !taken[e] && probs[e] > best) { best = probs[e]; bi = e; }
            taken[bi] = true; idx6[rr] = bi; w6[rr] = best;
        }
        float wm = -INFINITY;
        for (int rr = 0; rr < KK; ++rr) wm = fmaxf(wm, w6[rr]);
        float ws = 0.f;
        for (int rr = 0; rr < KK; ++rr) { w6[rr] = expf(w6[rr] - wm); ws += w6[rr]; }
        float winv = 1.f / ws;
        for (int rr = 0; rr < KK; ++rr) {
            w6[rr] *= winv;
            g_idx[t * KK + rr] = idx6[rr];
            g_w[t * KK + rr] = w6[rr];
            atomicAdd(&g_cnt[idx6[rr]], 1);
        }
        bool hit[DD];
        for (int d = 0; d < DD; ++d) hit[d] = false;
        for (int rr = 0; rr < KK; ++rr) hit[idx6[rr] >> 2] = true;
        for (int d = 0; d < DD; ++d)
            if (hit[d]) atomicAdd(&g_devhit[d], 1.0f);
    }
    __syncwarp();
    atomicAdd(&g_probsum[lane], probs[lane]);
}

__global__ void k_scan()
{
    int acc = 0;
    for (int e = 0; e < EE; ++e) {
        g_off[e] = acc;
        g_cur[e] = acc;
        acc += g_cnt[e];
    }
}

__global__ void k_build()
{
    int i = blockIdx.x * blockDim.x + threadIdx.x;
    if (i >= TOTSEL) return;
    int e = g_idx[i];
    int pos = atomicAdd(&g_cur[e], 1);
    g_tok[pos] = i / KK;
    g_wt[pos] = g_w[i];
}

// ---------------------------------------------------------------------------
// Final: out = rmsnorm(h1 + shared[z0] + shared[z1] + routed)
// ---------------------------------------------------------------------------
__global__ void k_final(float* __restrict__ out)
{
    __shared__ float ys[HH];
    __shared__ float red[256];
    const int r = blockIdx.x;
    float ss = 0.f;
    for (int i = threadIdx.x; i < HH; i += 256) {
        size_t p = (size_t)r * HH + i;
        float v = g_h1[p] + g_shared[p] + g_shared[(size_t)TT * HH + p] + g_routed[p];
        ys[i] = v;
        ss += v * v;
    }
    red[threadIdx.x] = ss;
    __syncthreads();
    for (int s = 128; s > 0; s >>= 1) {
        if (threadIdx.x < s) red[threadIdx.x] += red[threadIdx.x + s];
        __syncthreads();
    }
    float scale = rsqrtf(red[0] / (float)HH + EPSF);
    for (int i = threadIdx.x; i < HH; i += 256)
        out[(size_t)r * HH + i] = ys[i] * scale;
}

__global__ void k_aux(float* __restrict__ dst)
{
    float f_i[EE], P_i[EE];
    for (int e = 0; e < EE; ++e) {
        f_i[e] = (float)g_cnt[e] / ((float)TOTSEL + 1e-10f);
        P_i[e] = g_probsum[e] / (float)TT;
    }
    float eb = 0.f;
    for (int e = 0; e < EE; ++e) eb += f_i[e] * P_i[e];
    float expert_bal = fminf(eb * 0.003f, 10.f);

    float db = 0.f, cb = 0.f;
    for (int d = 0; d < DD; ++d) {
        float df = 0.f, dP = 0.f;
        for (int j = 0; j < EPD; ++j) { df += f_i[4*d + j]; dP += P_i[4*d + j]; }
        df *= 0.25f;
        db += df * dP;
        float fc = g_devhit[d] / ((float)(TT * KDD) + 1e-10f);
        cb += fc * dP;
    }
    float device_bal = fminf(db * 0.05f, 10.f);
    float comm_bal   = fminf(cb * 0.02f, 10.f);
    *dst = expert_bal + device_bal + comm_bal;
}

// ---------------------------------------------------------------------------
// Launch
// ---------------------------------------------------------------------------
extern "C" void kernel_launch(void* const* d_in, const int* in_sizes, int n_in,
                              void* d_out, int out_size)
{
    const float* x     = (const float*)d_in[0];
    const float* Wqkv  = (const float*)d_in[1];
    const float* Wo    = (const float*)d_in[2];
    const float* Wgu_s = (const float*)d_in[3];
    const float* Wd_s  = (const float*)d_in[4];
    const float* Wr    = (const float*)d_in[5];
    const float* Wgu   = (const float*)d_in[6];
    const float* Wd    = (const float*)d_in[7];
    float* out = (float*)d_out;

    cudaFuncSetAttribute(mma_gemm<0>, cudaFuncAttributeMaxDynamicSharedMemorySize, GSMEM);
    cudaFuncSetAttribute(mma_gemm<1>, cudaFuncAttributeMaxDynamicSharedMemorySize, GSMEM);
    cudaFuncSetAttribute(mma_gemm<2>, cudaFuncAttributeMaxDynamicSharedMemorySize, GSMEM);
    cudaFuncSetAttribute(k_attn2, cudaFuncAttributeMaxDynamicSharedMemorySize, ATT_SMEM);

    k_zero<<<(TT * HH + 255) / 256, 256>>>();

    // QKV: x @ Wqkv -> g_qkv
    mma_gemm<0><<<dim3(24, 16, 1), 256, GSMEM>>>(x, -1, BUF_QKV, Wqkv, 0, HH, 3 * HH, 0, 0);

    k_attn2<<<dim3(SS / AQB, NHH, BB), 128, ATT_SMEM>>>();

    // Wo: g_attn @ Wo -> g_attno
    mma_gemm<0><<<dim3(8, 16, 1), 256, GSMEM>>>(nullptr, BUF_ATTN, BUF_ATTNO, Wo, 0, HH, HH, 0, 0);

    k_addrms<<<TT, 256>>>(x);

    // Shared experts, batched over z=2:
    // GU: h1 @ Wgu_s[z] -> g_gu rows [z*TT, z*TT+TT)
    mma_gemm<0><<<dim3(24, 16, 2), 256, GSMEM>>>(nullptr, BUF_H1, BUF_GU,
                                                 Wgu_s, (long long)HH * GU, HH, GU, 0, TT);
    k_act<<<2048, 256>>>(2 * TT);
    // Down: g_act rows [z*TT..] @ Wd_s[z] -> g_shared halves
    mma_gemm<0><<<dim3(8, 16, 2), 256, GSMEM>>>(nullptr, BUF_ACT, BUF_SHARED,
                                                Wd_s, (long long)INTER * HH, INTER, HH, TT, TT);

    // Routing
    k_route<<<TT, 32>>>(Wr);
    k_scan<<<1, 1>>>();
    k_build<<<TOTSEL / 256, 256>>>();

    // Routed experts (grouped, gathered)
    mma_gemm<1><<<dim3(24, 16, EE), 256, GSMEM>>>(nullptr, -1, -1, Wgu, (long long)HH * GU, HH, GU, 0, 0);
    k_act<<<4096, 256>>>(TOTSEL);
    mma_gemm<2><<<dim3(8, 16, EE), 256, GSMEM>>>(nullptr, -1, -1, Wd, (long long)INTER * HH, INTER, HH, 0, 0);

    k_final<<<TT, 256>>>(out);

    if (out_size > TT * HH)
        k_aux<<<1, 1>>>(out + TT * HH);
}

// round 16
// speedup vs baseline: 1.5725x; 1.5725x over previous
#include <cuda_runtime.h>
#include <cuda_bf16.h>
#include <stdint.h>
#include <math.h>

// ---------------------------------------------------------------------------
// Problem constants
// ---------------------------------------------------------------------------
#define BB 2
#define SS 512
#define HH 1024
#define NHH 16
#define HD 64
#define TT (BB*SS)          // 1024 tokens
#define EE 32               // experts
#define DD 8                // devices
#define KK 6                // top-k experts
#define KDD 3               // top devices
#define EPD (EE/DD)         // 4 experts per device
#define INTER 1536
#define GU (2*INTER)        // 3072
#define EPSF 1e-5f
#define TOTSEL (TT*KK)      // 6144

// ---------------------------------------------------------------------------
// Scratch (static device globals; accessed ONLY by device-code symbol refs)
// ---------------------------------------------------------------------------
__device__ float g_qkv   [TT * 3 * HH];
__device__ float g_attno [TT * HH];
__device__ float g_h1    [TT * HH];          // fp32 (router + final)
__device__ float g_gu    [TOTSEL * GU];
__device__ float g_shared[TT * HH];
__device__ float g_routed[TT * HH];

// Pre-split bf16 hi/lo A-side operands (written by producer kernels)
__device__ __nv_bfloat16 g_xb0   [TT * HH],      g_xb1   [TT * HH];
__device__ __nv_bfloat16 g_h1b0  [TT * HH],      g_h1b1  [TT * HH];
__device__ __nv_bfloat16 g_attnb0[TT * HH],      g_attnb1[TT * HH];
__device__ __nv_bfloat16 g_actb0 [TOTSEL * INTER], g_actb1[TOTSEL * INTER];

__device__ int   g_idx   [TT * KK];
__device__ float g_w     [TT * KK];
__device__ int   g_cnt   [EE];
__device__ int   g_off   [EE];
__device__ int   g_cur   [EE];
__device__ int   g_tok   [TOTSEL];
__device__ float g_wt    [TOTSEL];
__device__ float g_probsum[EE];
__device__ float g_devhit [DD];

#define BUF_QKV    0
#define BUF_ATTNO  1
#define BUF_GU     2
#define BUF_SHARED 3
__device__ __forceinline__ float* devbuf(int id) {
    switch (id) {
        case BUF_QKV:    return g_qkv;
        case BUF_ATTNO:  return g_attno;
        case BUF_GU:     return g_gu;
        case BUF_SHARED: return g_shared;
        default:         return g_routed;
    }
}
#define AB_XB    0
#define AB_H1B   1
#define AB_ATTNB 2
#define AB_ACTB  3
__device__ __forceinline__ const __nv_bfloat16* devbufb(int id, int part) {
    switch (id) {
        case AB_XB:    return part ? g_xb1    : g_xb0;
        case AB_H1B:   return part ? g_h1b1   : g_h1b0;
        case AB_ATTNB: return part ? g_attnb1 : g_attnb0;
        default:       return part ? g_actb1  : g_actb0;
    }
}

// ---------------------------------------------------------------------------
// PTX helpers (base ISA: ldmatrix + mma.sync)
// ---------------------------------------------------------------------------
__device__ __forceinline__ uint32_t smem_u32(const void* p) {
    uint32_t a;
    asm("{ .reg .u64 t; cvta.to.shared.u64 t, %1; cvt.u32.u64 %0, t; }" : "=r"(a) : "l"(p));
    return a;
}
__device__ __forceinline__ void ldsm_x4(uint32_t& r0, uint32_t& r1, uint32_t& r2, uint32_t& r3,
                                        uint32_t addr) {
    asm volatile("ldmatrix.sync.aligned.m8n8.x4.shared.b16 {%0,%1,%2,%3}, [%4];"
                 : "=r"(r0), "=r"(r1), "=r"(r2), "=r"(r3) : "r"(addr));
}
__device__ __forceinline__ void ldsm_x4_t(uint32_t& r0, uint32_t& r1, uint32_t& r2, uint32_t& r3,
                                          uint32_t addr) {
    asm volatile("ldmatrix.sync.aligned.m8n8.x4.trans.shared.b16 {%0,%1,%2,%3}, [%4];"
                 : "=r"(r0), "=r"(r1), "=r"(r2), "=r"(r3) : "r"(addr));
}
__device__ __forceinline__ void mma_bf16(float* c, const uint32_t* a, const uint32_t* b) {
    asm volatile("mma.sync.aligned.m16n8k16.row.col.f32.bf16.bf16.f32 "
                 "{%0,%1,%2,%3}, {%4,%5,%6,%7}, {%8,%9}, {%0,%1,%2,%3};"
                 : "+f"(c[0]), "+f"(c[1]), "+f"(c[2]), "+f"(c[3])
                 : "r"(a[0]), "r"(a[1]), "r"(a[2]), "r"(a[3]), "r"(b[0]), "r"(b[1]));
}
// pack (lo_elem, hi_elem) -> bf16x2 (first arg in LOW half)
__device__ __forceinline__ uint32_t pk_bf16x2(float lo, float hi) {
    uint32_t r;
    asm("cvt.rn.bf16x2.f32 %0, %1, %2;" : "=r"(r) : "f"(hi), "f"(lo));
    return r;
}
// hi-halves of two fp32 packed into one u32 (x0 -> low half) — truncated bf16
__device__ __forceinline__ uint32_t hi_pack(float x0, float x1) {
    uint32_t r;
    asm("prmt.b32 %0, %1, %2, 0x7632;" : "=r"(r)
        : "r"(__float_as_uint(x0)), "r"(__float_as_uint(x1)));
    return r;
}
__device__ __forceinline__ float hi_of(float x) {
    return __uint_as_float(__float_as_uint(x) & 0xffff0000u);
}
// scalar split store: hi = trunc-bf16(v), lo = rn-bf16(v - hi)
__device__ __forceinline__ void store_split(__nv_bfloat16* hp, __nv_bfloat16* lp, float v) {
    __nv_bfloat16_raw hr;
    hr.x = (unsigned short)(__float_as_uint(v) >> 16);
    *hp = __nv_bfloat16(hr);
    *lp = __float2bfloat16(v - hi_of(v));
}

// ---------------------------------------------------------------------------
// bf16-split tensor-core GEMM:  C[M,N] = A[M,K] @ W[K,N]
//   A@B ~= Ahi*Bhi + Alo*Bhi + Ahi*Blo  (fp32 accum; hi=trunc, lo exact-残差)
// A arrives PRE-SPLIT as bf16 hi/lo global pairs (zero conversion in fill).
// B (fp32 weights) split in-fill via PRMT/Dekker (~3 instr/elem).
// MODE 0: plain | MODE 1: gather (g_h1b rows via g_tok) | MODE 2: scatter
// Tile 64x128x32, 256 threads (8 warps as 4x2).
// ---------------------------------------------------------------------------
#define BM 64
#define BN 128
#define BK 32
#define SA (BK + 8)         // 40 bf16 per A row
#define SB (BN + 8)         // 136 bf16 per B row

template<int MODE, bool ACCUM>
__global__ __launch_bounds__(256, 2)
void mma_gemm(int Aid, int Cid, const float* __restrict__ W, long long Wstride,
              int K, int N)
{
    __shared__ __align__(16) __nv_bfloat16 AH[BM][SA];
    __shared__ __align__(16) __nv_bfloat16 AL[BM][SA];
    __shared__ __align__(16) __nv_bfloat16 BHs[BK][SB];
    __shared__ __align__(16) __nv_bfloat16 BLs[BK][SB];

    const int tid  = threadIdx.x;
    const int lane = tid & 31;
    const int warp = tid >> 5;
    const int wm = warp >> 1;          // 0..3
    const int wn = warp & 1;           // 0..1
    const int m0 = blockIdx.y * BM;
    const int n0 = blockIdx.x * BN;
    const int z  = blockIdx.z;

    int cnt = 0, off = 0;
    if (MODE != 0) {
        cnt = g_cnt[z];
        off = g_off[z];
        if (m0 >= cnt) return;
    }
    const float* Wb = W + (size_t)z * (size_t)Wstride;

    // A fill: one 16B chunk of hi + one of lo per thread (64 rows x 32 elems)
    const int arow = tid >> 2;
    const int akc  = (tid & 3) * 8;
    const __nv_bfloat16* ah_src = nullptr;
    const __nv_bfloat16* al_src = nullptr;
    {
        const int lr = m0 + arow;
        if (MODE == 0) {
            ah_src = devbufb(Aid, 0) + (size_t)lr * (size_t)K + akc;
            al_src = devbufb(Aid, 1) + (size_t)lr * (size_t)K + akc;
        } else if (MODE == 1) {
            if (lr < cnt) {
                size_t ro = (size_t)g_tok[off + lr] * HH + akc;
                ah_src = g_h1b0 + ro;
                al_src = g_h1b1 + ro;
            }
        } else {
            if (lr < cnt) {
                size_t ro = (size_t)(off + lr) * (size_t)K + akc;
                ah_src = g_actb0 + ro;
                al_src = g_actb1 + ro;
            }
        }
    }

    // B fill coords: 4 float4 chunks per thread (32 rows x 128 cols fp32)
    int brow[4], bnc[4];
    #pragma unroll
    for (int i = 0; i < 4; ++i) {
        int ca = tid + i * 256;
        brow[i] = ca >> 5;
        bnc[i]  = (ca & 31) * 4;
    }

    float acc[8][4];
    #pragma unroll
    for (int j = 0; j < 8; ++j)
        #pragma unroll
        for (int c = 0; c < 4; ++c) acc[j][c] = 0.f;

    const int niter = K / BK;
    for (int it = 0; it < niter; ++it) {
        const int k0 = it * BK;
        // ---- A fill: raw bf16 copies ----
        uint4 hv = make_uint4(0u,0u,0u,0u), lv = make_uint4(0u,0u,0u,0u);
        if (ah_src) {
            hv = *(const uint4*)(ah_src + k0);
            lv = *(const uint4*)(al_src + k0);
        }
        *(uint4*)&AH[arow][akc] = hv;
        *(uint4*)&AL[arow][akc] = lv;
        // ---- B fill: fp32 load + PRMT/Dekker split ----
        #pragma unroll
        for (int i = 0; i < 4; ++i) {
            float4 bv = *(const float4*)(Wb + (size_t)(k0 + brow[i]) * (size_t)N + n0 + bnc[i]);
            *(uint2*)&BHs[brow[i]][bnc[i]] =
                make_uint2(hi_pack(bv.x, bv.y), hi_pack(bv.z, bv.w));
            *(uint2*)&BLs[brow[i]][bnc[i]] =
                make_uint2(pk_bf16x2(bv.x - hi_of(bv.x), bv.y - hi_of(bv.y)),
                           pk_bf16x2(bv.z - hi_of(bv.z), bv.w - hi_of(bv.w)));
        }
        __syncthreads();

        // ---- compute: 2 k16 steps ----
        #pragma unroll
        for (int s = 0; s < 2; ++s) {
            uint32_t ah[4], al[4], bh[4][4], bl[4][4];
            const int ar = lane & 15;
            const int ac = s * 16 + (lane >> 4) * 8;
            ldsm_x4(ah[0], ah[1], ah[2], ah[3], smem_u32(&AH[wm * 16 + ar][ac]));
            ldsm_x4(al[0], al[1], al[2], al[3], smem_u32(&AL[wm * 16 + ar][ac]));
            const int br = s * 16 + (lane & 15);
            #pragma unroll
            for (int g = 0; g < 4; ++g) {
                int bc = wn * 64 + g * 16 + (lane >> 4) * 8;
                ldsm_x4_t(bh[g][0], bh[g][1], bh[g][2], bh[g][3], smem_u32(&BHs[br][bc]));
                ldsm_x4_t(bl[g][0], bl[g][1], bl[g][2], bl[g][3], smem_u32(&BLs[br][bc]));
            }
            #pragma unroll
            for (int j = 0; j < 8; ++j) mma_bf16(acc[j], ah, &bh[j >> 1][(j & 1) * 2]);
            #pragma unroll
            for (int j = 0; j < 8; ++j) mma_bf16(acc[j], al, &bh[j >> 1][(j & 1) * 2]);
            #pragma unroll
            for (int j = 0; j < 8; ++j) mma_bf16(acc[j], ah, &bl[j >> 1][(j & 1) * 2]);
        }
        __syncthreads();
    }

    // ---- epilogue ----
    const int gq = lane >> 2;
    const int tq = lane & 3;
    const int rr0 = wm * 16 + gq;
    const int rr1 = rr0 + 8;
    #pragma unroll
    for (int j = 0; j < 8; ++j) {
        const int col = n0 + wn * 64 + j * 8 + tq * 2;
        float d0 = acc[j][0], d1 = acc[j][1], d2 = acc[j][2], d3 = acc[j][3];
        if (MODE == 0) {
            float* C = devbuf(Cid);
            float2* p0 = (float2*)&C[(size_t)(m0 + rr0) * (size_t)N + col];
            float2* p1 = (float2*)&C[(size_t)(m0 + rr1) * (size_t)N + col];
            if (ACCUM) {
                float2 o0 = *p0, o1 = *p1;
                *p0 = make_float2(o0.x + d0, o0.y + d1);
                *p1 = make_float2(o1.x + d2, o1.y + d3);
            } else {
                *p0 = make_float2(d0, d1);
                *p1 = make_float2(d2, d3);
            }
        } else if (MODE == 1) {
            if (m0 + rr0 < cnt)
                *(float2*)&g_gu[(size_t)(off + m0 + rr0) * (size_t)N + col] = make_float2(d0, d1);
            if (m0 + rr1 < cnt)
                *(float2*)&g_gu[(size_t)(off + m0 + rr1) * (size_t)N + col] = make_float2(d2, d3);
        } else {
            if (m0 + rr0 < cnt) {
                int token = g_tok[off + m0 + rr0];
                float wt  = g_wt[off + m0 + rr0];
                atomicAdd(&g_routed[(size_t)token * HH + col],     wt * d0);
                atomicAdd(&g_routed[(size_t)token * HH + col + 1], wt * d1);
            }
            if (m0 + rr1 < cnt) {
                int token = g_tok[off + m0 + rr1];
                float wt  = g_wt[off + m0 + rr1];
                atomicAdd(&g_routed[(size_t)token * HH + col],     wt * d2);
                atomicAdd(&g_routed[(size_t)token * HH + col + 1], wt * d3);
            }
        }
    }
}

// ---------------------------------------------------------------------------
// Zero-init (graph replays)
// ---------------------------------------------------------------------------
__global__ void k_zero() {
    int i = blockIdx.x * blockDim.x + threadIdx.x;
    if (i < TT * HH) g_routed[i] = 0.f;
    if (i < EE) { g_cnt[i] = 0; g_probsum[i] = 0.f; }
    if (i < DD) g_devhit[i] = 0.f;
}

// x -> bf16 hi/lo pair (pairs of elements per thread)
__global__ void k_cvt_x(const float* __restrict__ x)
{
    const int n = TT * HH / 2;
    for (int p = blockIdx.x * blockDim.x + threadIdx.x; p < n;
         p += gridDim.x * blockDim.x) {
        float2 v = *(const float2*)(x + 2 * p);
        *(uint32_t*)&g_xb0[2 * p] = hi_pack(v.x, v.y);
        *(uint32_t*)&g_xb1[2 * p] = pk_bf16x2(v.x - hi_of(v.x), v.y - hi_of(v.y));
    }
}

// ---------------------------------------------------------------------------
// Attention: block = 4 warps / 16 queries for one (b,h); writes bf16 hi/lo.
// ---------------------------------------------------------------------------
#define AQB 16
#define KTS 65
#define A_KT 0
#define A_QS (64 * KTS)
#define A_QSN (A_QS + AQB * 64)
#define ATT_SMEM ((A_QSN + AQB * SS) * 4)

__global__ void k_attn2()
{
    extern __shared__ float sm[];
    const int tid = threadIdx.x, lane = tid & 31, w = tid >> 5;
    const int q0 = blockIdx.x * AQB;
    const int h = blockIdx.y, b = blockIdx.z;
    const size_t base = (size_t)b * SS * 3 * HH + (size_t)h * HD;
    const int wq = w * 4;

    for (int i = tid; i < AQB * 16; i += 128) {
        int qi = i >> 4, dc = (i & 15) * 4;
        *(float4*)&sm[A_QS + qi * 64 + dc] =
            *(const float4*)(g_qkv + base + (size_t)(q0 + qi) * (3 * HH) + dc);
    }

    for (int t = 0; t < SS / 64; ++t) {
        __syncthreads();
        for (int i = tid; i < 64 * 16; i += 128) {
            int kr = i >> 4, dc = (i & 15) * 4;
            float4 kv = *(const float4*)(g_qkv + base + HH +
                                         (size_t)(t * 64 + kr) * (3 * HH) + dc);
            float* d = &sm[A_KT + kr * KTS + dc];
            d[0] = kv.x; d[1] = kv.y; d[2] = kv.z; d[3] = kv.w;
        }
        __syncthreads();
        float s0[4] = {0,0,0,0}, s1[4] = {0,0,0,0};
        #pragma unroll 4
        for (int d4 = 0; d4 < 16; ++d4) {
            const int d = d4 * 4;
            const float* k0p = &sm[A_KT + lane * KTS + d];
            const float* k1p = &sm[A_KT + (lane + 32) * KTS + d];
            float k00 = k0p[0], k01 = k0p[1], k02 = k0p[2], k03 = k0p[3];
            float k10 = k1p[0], k11 = k1p[1], k12 = k1p[2], k13 = k1p[3];
            #pragma unroll
            for (int j = 0; j < 4; ++j) {
                float4 qv = *(float4*)&sm[A_QS + (wq + j) * 64 + d];
                s0[j] += qv.x * k00 + qv.y * k01 + qv.z * k02 + qv.w * k03;
                s1[j] += qv.x * k10 + qv.y * k11 + qv.z * k12 + qv.w * k13;
            }
        }
        #pragma unroll
        for (int j = 0; j < 4; ++j) {
            sm[A_QSN + (wq + j) * SS + t * 64 + lane]      = s0[j] * 0.125f;
            sm[A_QSN + (wq + j) * SS + t * 64 + lane + 32] = s1[j] * 0.125f;
        }
    }
    __syncthreads();

    float inv[4];
    #pragma unroll
    for (int j = 0; j < 4; ++j) {
        float* row = &sm[A_QSN + (wq + j) * SS];
        float m = -INFINITY;
        for (int i = lane; i < SS; i += 32) m = fmaxf(m, row[i]);
        #pragma unroll
        for (int o = 16; o > 0; o >>= 1) m = fmaxf(m, __shfl_xor_sync(0xffffffffu, m, o));
        float sum = 0.f;
        for (int i = lane; i < SS; i += 32) {
            float p = expf(row[i] - m);
            row[i] = p;
            sum += p;
        }
        #pragma unroll
        for (int o = 16; o > 0; o >>= 1) sum += __shfl_xor_sync(0xffffffffu, sum, o);
        inv[j] = 1.f / sum;
    }

    float2 acc[4] = {{0.f,0.f},{0.f,0.f},{0.f,0.f},{0.f,0.f}};
    for (int t = 0; t < SS / 64; ++t) {
        __syncthreads();
        for (int i = tid; i < 64 * 16; i += 128) {
            int kr = i >> 4, dc = (i & 15) * 4;
            float4 vv = *(const float4*)(g_qkv + base + 2 * HH +
                                         (size_t)(t * 64 + kr) * (3 * HH) + dc);
            float* d = &sm[A_KT + kr * KTS + dc];
            d[0] = vv.x; d[1] = vv.y; d[2] = vv.z; d[3] = vv.w;
        }
        __syncthreads();
        #pragma unroll 4
        for (int kk = 0; kk < 64; ++kk) {
            float vx = sm[A_KT + kk * KTS + lane];
            float vy = sm[A_KT + kk * KTS + lane + 32];
            #pragma unroll
            for (int j = 0; j < 4; ++j) {
                float pp = sm[A_QSN + (wq + j) * SS + t * 64 + kk];
                acc[j].x += pp * vx;
                acc[j].y += pp * vy;
            }
        }
    }

    #pragma unroll
    for (int j = 0; j < 4; ++j) {
        size_t o = (size_t)(b * SS + q0 + wq + j) * HH + h * HD;
        store_split(&g_attnb0[o + lane],      &g_attnb1[o + lane],      acc[j].x * inv[j]);
        store_split(&g_attnb0[o + lane + 32], &g_attnb1[o + lane + 32], acc[j].y * inv[j]);
    }
}

// ---------------------------------------------------------------------------
// h1 = rmsnorm(x + attno): writes fp32 h1 AND bf16 hi/lo pair
// ---------------------------------------------------------------------------
__global__ void k_addrms(const float* __restrict__ x)
{
    __shared__ float ys[HH];
    __shared__ float red[256];
    const int r = blockIdx.x;
    float ss = 0.f;
    for (int i = threadIdx.x * 2; i < HH; i += 512) {
        float v0 = x[(size_t)r * HH + i]     + g_attno[(size_t)r * HH + i];
        float v1 = x[(size_t)r * HH + i + 1] + g_attno[(size_t)r * HH + i + 1];
        ys[i] = v0; ys[i + 1] = v1;
        ss += v0 * v0 + v1 * v1;
    }
    red[threadIdx.x] = ss;
    __syncthreads();
    for (int s = 128; s > 0; s >>= 1) {
        if (threadIdx.x < s) red[threadIdx.x] += red[threadIdx.x + s];
        __syncthreads();
    }
    float scale = rsqrtf(red[0] / (float)HH + EPSF);
    for (int i = threadIdx.x * 2; i < HH; i += 512) {
        float v0 = ys[i] * scale, v1 = ys[i + 1] * scale;
        *(float2*)&g_h1[(size_t)r * HH + i] = make_float2(v0, v1);
        *(uint32_t*)&g_h1b0[(size_t)r * HH + i] = hi_pack(v0, v1);
        *(uint32_t*)&g_h1b1[(size_t)r * HH + i] =
            pk_bf16x2(v0 - hi_of(v0), v1 - hi_of(v1));
    }
}

// ---------------------------------------------------------------------------
// SwiGLU activation: g_gu fp32 -> g_actb bf16 hi/lo
// ---------------------------------------------------------------------------
__global__ void k_act(int rows)
{
    const long long n = (long long)rows * (INTER / 2);
    for (long long p = (long long)blockIdx.x * blockDim.x + threadIdx.x;
         p < n; p += (long long)gridDim.x * blockDim.x) {
        long long r = p / (INTER / 2);
        int j = (int)(p % (INTER / 2)) * 2;
        const float* gp = &g_gu[r * GU + j];
        float g0 = gp[0], g1 = gp[1];
        float u0 = gp[INTER], u1 = gp[INTER + 1];
        float v0 = g0 / (1.f + expf(-g0)) * u0;
        float v1 = g1 / (1.f + expf(-g1)) * u1;
        *(uint32_t*)&g_actb0[r * INTER + j] = hi_pack(v0, v1);
        *(uint32_t*)&g_actb1[r * INTER + j] =
            pk_bf16x2(v0 - hi_of(v0), v1 - hi_of(v1));
    }
}

// ---------------------------------------------------------------------------
// Router: one warp per token.
// ---------------------------------------------------------------------------
__global__ void k_route(const float* __restrict__ Wr)
{
    __shared__ float xr[HH];
    __shared__ float logit_s[EE];
    __shared__ float probs[EE];
    const int t = blockIdx.x;
    const int lane = threadIdx.x;

    for (int i = lane; i < HH; i += 32) xr[i] = g_h1[(size_t)t * HH + i];
    __syncwarp();
    float acc = 0.f;
    for (int hh = 0; hh < HH; ++hh)
        acc = fmaf(xr[hh], Wr[(size_t)hh * EE + lane], acc);
    logit_s[lane] = acc;
    __syncwarp();

    if (lane == 0) {
        float m = -INFINITY;
        for (int e = 0; e < EE; ++e) m = fmaxf(m, logit_s[e]);
        float s = 0.f;
        for (int e = 0; e < EE; ++e) { float p = expf(logit_s[e] - m); probs[e] = p; s += p; }
        float inv = 1.f / s;
        for (int e = 0; e < EE; ++e) probs[e] *= inv;

        float dev[DD];
        for (int d = 0; d < DD; ++d)
            dev[d] = probs[4*d] + probs[4*d+1] + probs[4*d+2] + probs[4*d+3];
        bool devsel[DD];
        for (int d = 0; d < DD; ++d) devsel[d] = false;
        for (int rr = 0; rr < KDD; ++rr) {
            float best = -INFINITY; int bi = -1;
            for (int d = 0; d < DD; ++d)
                if (!devsel[d] && dev[d] > best) { best = dev[d]; bi = d; }
            devsel[bi] = true;
        }
        int idx6[KK]; float w6[KK];
        bool taken[EE];
        for (int e = 0; e < EE; ++e) taken[e] = false;
        for (int rr = 0; rr < KK; ++rr) {
            float best = -INFINITY; int bi = -1;
            for (int e = 0; e < EE; ++e)
                if (devsel[e >> 2] && !taken[e] && probs[e] > best) { best = probs[e]; bi = e; }
            taken[bi] = true; idx6[rr] = bi; w6[rr] = best;
        }
        float wm = -INFINITY;
        for (int rr = 0; rr < KK; ++rr) wm = fmaxf(wm, w6[rr]);
        float ws = 0.f;
        for (int rr = 0; rr < KK; ++rr) { w6[rr] = expf(w6[rr] - wm); ws += w6[rr]; }
        float winv = 1.f / ws;
        for (int rr = 0; rr < KK; ++rr) {
            w6[rr] *= winv;
            g_idx[t * KK + rr] = idx6[rr];
            g_w[t * KK + rr] = w6[rr];
            atomicAdd(&g_cnt[idx6[rr]], 1);
        }
        bool hit[DD];
        for (int d = 0; d < DD; ++d) hit[d] = false;
        for (int rr = 0; rr < KK; ++rr) hit[idx6[rr] >> 2] = true;
        for (int d = 0; d < DD; ++d)
            if (hit[d]) atomicAdd(&g_devhit[d], 1.0f);
    }
    __syncwarp();
    atomicAdd(&g_probsum[lane], probs[lane]);
}

__global__ void k_scan()
{
    int acc = 0;
    for (int e = 0; e < EE; ++e) {
        g_off[e] = acc;
        g_cur[e] = acc;
        acc += g_cnt[e];
    }
}

__global__ void k_build()
{
    int i = blockIdx.x * blockDim.x + threadIdx.x;
    if (i >= TOTSEL) return;
    int e = g_idx[i];
    int pos = atomicAdd(&g_cur[e], 1);
    g_tok[pos] = i / KK;
    g_wt[pos] = g_w[i];
}

// ---------------------------------------------------------------------------
// Final: out = rmsnorm(h1 + shared + routed)
// ---------------------------------------------------------------------------
__global__ void k_final(float* __restrict__ out)
{
    __shared__ float ys[HH];
    __shared__ float red[256];
    const int r = blockIdx.x;
    float ss = 0.f;
    for (int i = threadIdx.x; i < HH; i += 256) {
        size_t p = (size_t)r * HH + i;
        float v = g_h1[p] + g_shared[p] + g_routed[p];
        ys[i] = v;
        ss += v * v;
    }
    red[threadIdx.x] = ss;
    __syncthreads();
    for (int s = 128; s > 0; s >>= 1) {
        if (threadIdx.x < s) red[threadIdx.x] += red[threadIdx.x + s];
        __syncthreads();
    }
    float scale = rsqrtf(red[0] / (float)HH + EPSF);
    for (int i = threadIdx.x; i < HH; i += 256)
        out[(size_t)r * HH + i] = ys[i] * scale;
}

__global__ void k_aux(float* __restrict__ dst)
{
    float f_i[EE], P_i[EE];
    for (int e = 0; e < EE; ++e) {
        f_i[e] = (float)g_cnt[e] / ((float)TOTSEL + 1e-10f);
        P_i[e] = g_probsum[e] / (float)TT;
    }
    float eb = 0.f;
    for (int e = 0; e < EE; ++e) eb += f_i[e] * P_i[e];
    float expert_bal = fminf(eb * 0.003f, 10.f);

    float db = 0.f, cb = 0.f;
    for (int d = 0; d < DD; ++d) {
        float df = 0.f, dP = 0.f;
        for (int j = 0; j < EPD; ++j) { df += f_i[4*d + j]; dP += P_i[4*d + j]; }
        df *= 0.25f;
        db += df * dP;
        float fc = g_devhit[d] / ((float)(TT * KDD) + 1e-10f);
        cb += fc * dP;
    }
    float device_bal = fminf(db * 0.05f, 10.f);
    float comm_bal   = fminf(cb * 0.02f, 10.f);
    *dst = expert_bal + device_bal + comm_bal;
}

// ---------------------------------------------------------------------------
// Launch
// ---------------------------------------------------------------------------
extern "C" void kernel_launch(void* const* d_in, const int* in_sizes, int n_in,
                              void* d_out, int out_size)
{
    const float* x     = (const float*)d_in[0];
    const float* Wqkv  = (const float*)d_in[1];
    const float* Wo    = (const float*)d_in[2];
    const float* Wgu_s = (const float*)d_in[3];
    const float* Wd_s  = (const float*)d_in[4];
    const float* Wr    = (const float*)d_in[5];
    const float* Wgu   = (const float*)d_in[6];
    const float* Wd    = (const float*)d_in[7];
    float* out = (float*)d_out;

    cudaFuncSetAttribute(k_attn2, cudaFuncAttributeMaxDynamicSharedMemorySize, ATT_SMEM);

    k_zero<<<(TT * HH + 255) / 256, 256>>>();
    k_cvt_x<<<512, 256>>>(x);

    // QKV: xb @ Wqkv -> g_qkv
    mma_gemm<0, false><<<dim3(24, 16, 1), 256>>>(AB_XB, BUF_QKV, Wqkv, 0, HH, 3 * HH);

    k_attn2<<<dim3(SS / AQB, NHH, BB), 128, ATT_SMEM>>>();

    // Wo: attnb @ Wo -> g_attno
    mma_gemm<0, false><<<dim3(8, 16, 1), 256>>>(AB_ATTNB, BUF_ATTNO, Wo, 0, HH, HH);

    k_addrms<<<TT, 256>>>(x);

    // Shared expert 0
    mma_gemm<0, false><<<dim3(24, 16, 1), 256>>>(AB_H1B, BUF_GU, Wgu_s, 0, HH, GU);
    k_act<<<512, 256>>>(TT);
    mma_gemm<0, false><<<dim3(8, 16, 1), 256>>>(AB_ACTB, BUF_SHARED, Wd_s, 0, INTER, HH);

    // Shared expert 1 (accumulate)
    mma_gemm<0, false><<<dim3(24, 16, 1), 256>>>(AB_H1B, BUF_GU,
                                                 Wgu_s + (size_t)HH * GU, 0, HH, GU);
    k_act<<<512, 256>>>(TT);
    mma_gemm<0, true ><<<dim3(8, 16, 1), 256>>>(AB_ACTB, BUF_SHARED,
                                                Wd_s + (size_t)INTER * HH, 0, INTER, HH);

    // Routing
    k_route<<<TT, 32>>>(Wr);
    k_scan<<<1, 1>>>();
    k_build<<<TOTSEL / 256, 256>>>();

    // Routed experts (grouped, gathered)
    mma_gemm<1, false><<<dim3(24, 16, EE), 256>>>(-1, -1, Wgu, (long long)HH * GU, HH, GU);
    k_act<<<2048, 256>>>(TOTSEL);
    mma_gemm<2, false><<<dim3(8, 16, EE), 256>>>(-1, -1, Wd, (long long)INTER * HH, INTER, HH);

    k_final<<<TT, 256>>>(out);

    if (out_size > TT * HH)
        k_aux<<<1, 1>>>(out + TT * HH);
}

// round 17
// speedup vs baseline: 1.6816x; 1.0694x over previous
#include <cuda_runtime.h>
#include <cuda_bf16.h>
#include <stdint.h>
#include <math.h>

// ---------------------------------------------------------------------------
// Problem constants
// ---------------------------------------------------------------------------
#define BB 2
#define SS 512
#define HH 1024
#define NHH 16
#define HD 64
#define TT (BB*SS)          // 1024 tokens
#define EE 32               // experts
#define DD 8                // devices
#define KK 6                // top-k experts
#define KDD 3               // top devices
#define EPD (EE/DD)         // 4 experts per device
#define INTER 1536
#define GU (2*INTER)        // 3072
#define EPSF 1e-5f
#define TOTSEL (TT*KK)      // 6144

// ---------------------------------------------------------------------------
// Scratch (static device globals; accessed ONLY by device-code symbol refs)
// ---------------------------------------------------------------------------
__device__ float g_qkv   [TT * 3 * HH];
__device__ float g_attno [TT * HH];
__device__ float g_h1    [TT * HH];          // fp32 (router + final)
__device__ float g_gu    [TOTSEL * GU];
__device__ float g_shared[2 * TT * HH];      // two z-halves, summed in k_final
__device__ float g_routed[TT * HH];

// Pre-split bf16 hi/lo A-side operands (written by producer kernels)
__device__ __nv_bfloat16 g_xb0   [TT * HH],      g_xb1   [TT * HH];
__device__ __nv_bfloat16 g_h1b0  [TT * HH],      g_h1b1  [TT * HH];
__device__ __nv_bfloat16 g_attnb0[TT * HH],      g_attnb1[TT * HH];
__device__ __nv_bfloat16 g_actb0 [TOTSEL * INTER], g_actb1[TOTSEL * INTER];

__device__ int   g_idx   [TT * KK];
__device__ float g_w     [TT * KK];
__device__ int   g_cnt   [EE];
__device__ int   g_off   [EE];
__device__ int   g_cur   [EE];
__device__ int   g_tok   [TOTSEL];
__device__ float g_wt    [TOTSEL];
__device__ float g_probsum[EE];
__device__ float g_devhit [DD];

#define BUF_QKV    0
#define BUF_ATTNO  1
#define BUF_GU     2
#define BUF_SHARED 3
__device__ __forceinline__ float* devbuf(int id) {
    switch (id) {
        case BUF_QKV:    return g_qkv;
        case BUF_ATTNO:  return g_attno;
        case BUF_GU:     return g_gu;
        case BUF_SHARED: return g_shared;
        default:         return g_routed;
    }
}
#define AB_XB    0
#define AB_H1B   1
#define AB_ATTNB 2
#define AB_ACTB  3
__device__ __forceinline__ const __nv_bfloat16* devbufb(int id, int part) {
    switch (id) {
        case AB_XB:    return part ? g_xb1    : g_xb0;
        case AB_H1B:   return part ? g_h1b1   : g_h1b0;
        case AB_ATTNB: return part ? g_attnb1 : g_attnb0;
        default:       return part ? g_actb1  : g_actb0;
    }
}

// ---------------------------------------------------------------------------
// PTX helpers (base ISA: ldmatrix + mma.sync)
// ---------------------------------------------------------------------------
__device__ __forceinline__ uint32_t smem_u32(const void* p) {
    uint32_t a;
    asm("{ .reg .u64 t; cvta.to.shared.u64 t, %1; cvt.u32.u64 %0, t; }" : "=r"(a) : "l"(p));
    return a;
}
__device__ __forceinline__ void ldsm_x4(uint32_t& r0, uint32_t& r1, uint32_t& r2, uint32_t& r3,
                                        uint32_t addr) {
    asm volatile("ldmatrix.sync.aligned.m8n8.x4.shared.b16 {%0,%1,%2,%3}, [%4];"
                 : "=r"(r0), "=r"(r1), "=r"(r2), "=r"(r3) : "r"(addr));
}
__device__ __forceinline__ void ldsm_x4_t(uint32_t& r0, uint32_t& r1, uint32_t& r2, uint32_t& r3,
                                          uint32_t addr) {
    asm volatile("ldmatrix.sync.aligned.m8n8.x4.trans.shared.b16 {%0,%1,%2,%3}, [%4];"
                 : "=r"(r0), "=r"(r1), "=r"(r2), "=r"(r3) : "r"(addr));
}
__device__ __forceinline__ void mma_bf16(float* c, const uint32_t* a, const uint32_t* b) {
    asm volatile("mma.sync.aligned.m16n8k16.row.col.f32.bf16.bf16.f32 "
                 "{%0,%1,%2,%3}, {%4,%5,%6,%7}, {%8,%9}, {%0,%1,%2,%3};"
                 : "+f"(c[0]), "+f"(c[1]), "+f"(c[2]), "+f"(c[3])
                 : "r"(a[0]), "r"(a[1]), "r"(a[2]), "r"(a[3]), "r"(b[0]), "r"(b[1]));
}
// pack (lo_elem, hi_elem) -> bf16x2 (first arg in LOW half)
__device__ __forceinline__ uint32_t pk_bf16x2(float lo, float hi) {
    uint32_t r;
    asm("cvt.rn.bf16x2.f32 %0, %1, %2;" : "=r"(r) : "f"(hi), "f"(lo));
    return r;
}
// hi-halves of two fp32 packed into one u32 (x0 -> low half) — truncated bf16
__device__ __forceinline__ uint32_t hi_pack(float x0, float x1) {
    uint32_t r;
    asm("prmt.b32 %0, %1, %2, 0x7632;" : "=r"(r)
        : "r"(__float_as_uint(x0)), "r"(__float_as_uint(x1)));
    return r;
}
__device__ __forceinline__ float hi_of(float x) {
    return __uint_as_float(__float_as_uint(x) & 0xffff0000u);
}
// scalar split store: hi = trunc-bf16(v), lo = rn-bf16(v - hi)
__device__ __forceinline__ void store_split(__nv_bfloat16* hp, __nv_bfloat16* lp, float v) {
    __nv_bfloat16_raw hr;
    hr.x = (unsigned short)(__float_as_uint(v) >> 16);
    *hp = __nv_bfloat16(hr);
    *lp = __float2bfloat16(v - hi_of(v));
}

// ---------------------------------------------------------------------------
// bf16-split tensor-core GEMM:  C[M,N] = A[M,K] @ W[K,N]
//   A@B ~= Ahi*Bhi + Alo*Bhi + Ahi*Blo  (fp32 accum; hi=trunc, lo exact resid)
// A arrives PRE-SPLIT as bf16 hi/lo global pairs (zero conversion in fill).
// B (fp32 weights) split in-fill via PRMT/Dekker.
// MODE 0: plain, z-batched via AzR/CzR row offsets | MODE 1: gather | MODE 2: scatter
// Tile 64x128x32, 256 threads (8 warps as 4x2).
// ---------------------------------------------------------------------------
#define BM 64
#define BN 128
#define BK 32
#define SA (BK + 8)         // 40 bf16 per A row
#define SB (BN + 8)         // 136 bf16 per B row

template<int MODE, bool ACCUM>
__global__ __launch_bounds__(256, 2)
void mma_gemm(int Aid, int Cid, const float* __restrict__ W, long long Wstride,
              int K, int N, int AzR, int CzR)
{
    __shared__ __align__(16) __nv_bfloat16 AH[BM][SA];
    __shared__ __align__(16) __nv_bfloat16 AL[BM][SA];
    __shared__ __align__(16) __nv_bfloat16 BHs[BK][SB];
    __shared__ __align__(16) __nv_bfloat16 BLs[BK][SB];

    const int tid  = threadIdx.x;
    const int lane = tid & 31;
    const int warp = tid >> 5;
    const int wm = warp >> 1;          // 0..3
    const int wn = warp & 1;           // 0..1
    const int m0 = blockIdx.y * BM;
    const int n0 = blockIdx.x * BN;
    const int z  = blockIdx.z;

    int cnt = 0, off = 0;
    if (MODE != 0) {
        cnt = g_cnt[z];
        off = g_off[z];
        if (m0 >= cnt) return;
    }
    const float* Wb = W + (size_t)z * (size_t)Wstride;

    // A fill: one 16B chunk of hi + one of lo per thread (64 rows x 32 elems)
    const int arow = tid >> 2;
    const int akc  = (tid & 3) * 8;
    const __nv_bfloat16* ah_src = nullptr;
    const __nv_bfloat16* al_src = nullptr;
    {
        const int lr = m0 + arow;
        if (MODE == 0) {
            size_t ro = (size_t)(z * AzR + lr) * (size_t)K + akc;
            ah_src = devbufb(Aid, 0) + ro;
            al_src = devbufb(Aid, 1) + ro;
        } else if (MODE == 1) {
            if (lr < cnt) {
                size_t ro = (size_t)g_tok[off + lr] * HH + akc;
                ah_src = g_h1b0 + ro;
                al_src = g_h1b1 + ro;
            }
        } else {
            if (lr < cnt) {
                size_t ro = (size_t)(off + lr) * (size_t)K + akc;
                ah_src = g_actb0 + ro;
                al_src = g_actb1 + ro;
            }
        }
    }

    // B fill coords: 4 float4 chunks per thread (32 rows x 128 cols fp32)
    int brow[4], bnc[4];
    #pragma unroll
    for (int i = 0; i < 4; ++i) {
        int ca = tid + i * 256;
        brow[i] = ca >> 5;
        bnc[i]  = (ca & 31) * 4;
    }

    float acc[8][4];
    #pragma unroll
    for (int j = 0; j < 8; ++j)
        #pragma unroll
        for (int c = 0; c < 4; ++c) acc[j][c] = 0.f;

    const int niter = K / BK;
    for (int it = 0; it < niter; ++it) {
        const int k0 = it * BK;
        // ---- A fill: raw bf16 copies ----
        uint4 hv = make_uint4(0u,0u,0u,0u), lv = make_uint4(0u,0u,0u,0u);
        if (ah_src) {
            hv = *(const uint4*)(ah_src + k0);
            lv = *(const uint4*)(al_src + k0);
        }
        *(uint4*)&AH[arow][akc] = hv;
        *(uint4*)&AL[arow][akc] = lv;
        // ---- B fill: fp32 load + PRMT/Dekker split ----
        #pragma unroll
        for (int i = 0; i < 4; ++i) {
            float4 bv = *(const float4*)(Wb + (size_t)(k0 + brow[i]) * (size_t)N + n0 + bnc[i]);
            *(uint2*)&BHs[brow[i]][bnc[i]] =
                make_uint2(hi_pack(bv.x, bv.y), hi_pack(bv.z, bv.w));
            *(uint2*)&BLs[brow[i]][bnc[i]] =
                make_uint2(pk_bf16x2(bv.x - hi_of(bv.x), bv.y - hi_of(bv.y)),
                           pk_bf16x2(bv.z - hi_of(bv.z), bv.w - hi_of(bv.w)));
        }
        __syncthreads();

        // ---- compute: 2 k16 steps ----
        #pragma unroll
        for (int s = 0; s < 2; ++s) {
            uint32_t ah[4], al[4], bh[4][4], bl[4][4];
            const int ar = lane & 15;
            const int ac = s * 16 + (lane >> 4) * 8;
            ldsm_x4(ah[0], ah[1], ah[2], ah[3], smem_u32(&AH[wm * 16 + ar][ac]));
            ldsm_x4(al[0], al[1], al[2], al[3], smem_u32(&AL[wm * 16 + ar][ac]));
            const int br = s * 16 + (lane & 15);
            #pragma unroll
            for (int g = 0; g < 4; ++g) {
                int bc = wn * 64 + g * 16 + (lane >> 4) * 8;
                ldsm_x4_t(bh[g][0], bh[g][1], bh[g][2], bh[g][3], smem_u32(&BHs[br][bc]));
                ldsm_x4_t(bl[g][0], bl[g][1], bl[g][2], bl[g][3], smem_u32(&BLs[br][bc]));
            }
            #pragma unroll
            for (int j = 0; j < 8; ++j) mma_bf16(acc[j], ah, &bh[j >> 1][(j & 1) * 2]);
            #pragma unroll
            for (int j = 0; j < 8; ++j) mma_bf16(acc[j], al, &bh[j >> 1][(j & 1) * 2]);
            #pragma unroll
            for (int j = 0; j < 8; ++j) mma_bf16(acc[j], ah, &bl[j >> 1][(j & 1) * 2]);
        }
        __syncthreads();
    }

    // ---- epilogue ----
    const int gq = lane >> 2;
    const int tq = lane & 3;
    const int rr0 = wm * 16 + gq;
    const int rr1 = rr0 + 8;
    #pragma unroll
    for (int j = 0; j < 8; ++j) {
        const int col = n0 + wn * 64 + j * 8 + tq * 2;
        float d0 = acc[j][0], d1 = acc[j][1], d2 = acc[j][2], d3 = acc[j][3];
        if (MODE == 0) {
            float* C = devbuf(Cid) + (size_t)z * (size_t)CzR * (size_t)N;
            float2* p0 = (float2*)&C[(size_t)(m0 + rr0) * (size_t)N + col];
            float2* p1 = (float2*)&C[(size_t)(m0 + rr1) * (size_t)N + col];
            if (ACCUM) {
                float2 o0 = *p0, o1 = *p1;
                *p0 = make_float2(o0.x + d0, o0.y + d1);
                *p1 = make_float2(o1.x + d2, o1.y + d3);
            } else {
                *p0 = make_float2(d0, d1);
                *p1 = make_float2(d2, d3);
            }
        } else if (MODE == 1) {
            if (m0 + rr0 < cnt)
                *(float2*)&g_gu[(size_t)(off + m0 + rr0) * (size_t)N + col] = make_float2(d0, d1);
            if (m0 + rr1 < cnt)
                *(float2*)&g_gu[(size_t)(off + m0 + rr1) * (size_t)N + col] = make_float2(d2, d3);
        } else {
            if (m0 + rr0 < cnt) {
                int token = g_tok[off + m0 + rr0];
                float wt  = g_wt[off + m0 + rr0];
                atomicAdd(&g_routed[(size_t)token * HH + col],     wt * d0);
                atomicAdd(&g_routed[(size_t)token * HH + col + 1], wt * d1);
            }
            if (m0 + rr1 < cnt) {
                int token = g_tok[off + m0 + rr1];
                float wt  = g_wt[off + m0 + rr1];
                atomicAdd(&g_routed[(size_t)token * HH + col],     wt * d2);
                atomicAdd(&g_routed[(size_t)token * HH + col + 1], wt * d3);
            }
        }
    }
}

// ---------------------------------------------------------------------------
// Zero-init (graph replays)
// ---------------------------------------------------------------------------
__global__ void k_zero() {
    int i = blockIdx.x * blockDim.x + threadIdx.x;
    if (i < TT * HH) g_routed[i] = 0.f;
    if (i < EE) { g_cnt[i] = 0; g_probsum[i] = 0.f; }
    if (i < DD) g_devhit[i] = 0.f;
}

// x -> bf16 hi/lo pair (pairs of elements per thread)
__global__ void k_cvt_x(const float* __restrict__ x)
{
    const int n = TT * HH / 2;
    for (int p = blockIdx.x * blockDim.x + threadIdx.x; p < n;
         p += gridDim.x * blockDim.x) {
        float2 v = *(const float2*)(x + 2 * p);
        *(uint32_t*)&g_xb0[2 * p] = hi_pack(v.x, v.y);
        *(uint32_t*)&g_xb1[2 * p] = pk_bf16x2(v.x - hi_of(v.x), v.y - hi_of(v.y));
    }
}

// ---------------------------------------------------------------------------
// Attention: block = 8 warps / 32 queries for one (b,h). Each warp owns 4
// queries. K/V tiles staged in smem (shared by all warps). smem ~88 KB,
// 1 CTA/SM but 8 resident warps (was 4).
// ---------------------------------------------------------------------------
#define AQB 32
#define ATHR 256
#define KTS 65
#define A_KT 0
#define A_QS (64 * KTS)                 // 4160
#define A_QSN (A_QS + AQB * 64)         // 6208
#define ATT_SMEM ((A_QSN + AQB * SS) * 4)

__global__ void k_attn2()
{
    extern __shared__ float sm[];
    const int tid = threadIdx.x, lane = tid & 31, w = tid >> 5;
    const int q0 = blockIdx.x * AQB;
    const int h = blockIdx.y, b = blockIdx.z;
    const size_t base = (size_t)b * SS * 3 * HH + (size_t)h * HD;
    const int wq = w * 4;

    for (int i = tid; i < AQB * 16; i += ATHR) {
        int qi = i >> 4, dc = (i & 15) * 4;
        *(float4*)&sm[A_QS + qi * 64 + dc] =
            *(const float4*)(g_qkv + base + (size_t)(q0 + qi) * (3 * HH) + dc);
    }

    for (int t = 0; t < SS / 64; ++t) {
        __syncthreads();
        for (int i = tid; i < 64 * 16; i += ATHR) {
            int kr = i >> 4, dc = (i & 15) * 4;
            float4 kv = *(const float4*)(g_qkv + base + HH +
                                         (size_t)(t * 64 + kr) * (3 * HH) + dc);
            float* d = &sm[A_KT + kr * KTS + dc];
            d[0] = kv.x; d[1] = kv.y; d[2] = kv.z; d[3] = kv.w;
        }
        __syncthreads();
        float s0[4] = {0,0,0,0}, s1[4] = {0,0,0,0};
        #pragma unroll 4
        for (int d4 = 0; d4 < 16; ++d4) {
            const int d = d4 * 4;
            const float* k0p = &sm[A_KT + lane * KTS + d];
            const float* k1p = &sm[A_KT + (lane + 32) * KTS + d];
            float k00 = k0p[0], k01 = k0p[1], k02 = k0p[2], k03 = k0p[3];
            float k10 = k1p[0], k11 = k1p[1], k12 = k1p[2], k13 = k1p[3];
            #pragma unroll
            for (int j = 0; j < 4; ++j) {
                float4 qv = *(float4*)&sm[A_QS + (wq + j) * 64 + d];
                s0[j] += qv.x * k00 + qv.y * k01 + qv.z * k02 + qv.w * k03;
                s1[j] += qv.x * k10 + qv.y * k11 + qv.z * k12 + qv.w * k13;
            }
        }
        #pragma unroll
        for (int j = 0; j < 4; ++j) {
            sm[A_QSN + (wq + j) * SS + t * 64 + lane]      = s0[j] * 0.125f;
            sm[A_QSN + (wq + j) * SS + t * 64 + lane + 32] = s1[j] * 0.125f;
        }
    }
    __syncthreads();

    float inv[4];
    #pragma unroll
    for (int j = 0; j < 4; ++j) {
        float* row = &sm[A_QSN + (wq + j) * SS];
        float m = -INFINITY;
        for (int i = lane; i < SS; i += 32) m = fmaxf(m, row[i]);
        #pragma unroll
        for (int o = 16; o > 0; o >>= 1) m = fmaxf(m, __shfl_xor_sync(0xffffffffu, m, o));
        float sum = 0.f;
        for (int i = lane; i < SS; i += 32) {
            float p = expf(row[i] - m);
            row[i] = p;
            sum += p;
        }
        #pragma unroll
        for (int o = 16; o > 0; o >>= 1) sum += __shfl_xor_sync(0xffffffffu, sum, o);
        inv[j] = 1.f / sum;
    }

    float2 acc[4] = {{0.f,0.f},{0.f,0.f},{0.f,0.f},{0.f,0.f}};
    for (int t = 0; t < SS / 64; ++t) {
        __syncthreads();
        for (int i = tid; i < 64 * 16; i += ATHR) {
            int kr = i >> 4, dc = (i & 15) * 4;
            float4 vv = *(const float4*)(g_qkv + base + 2 * HH +
                                         (size_t)(t * 64 + kr) * (3 * HH) + dc);
            float* d = &sm[A_KT + kr * KTS + dc];
            d[0] = vv.x; d[1] = vv.y; d[2] = vv.z; d[3] = vv.w;
        }
        __syncthreads();
        #pragma unroll 4
        for (int kk = 0; kk < 64; ++kk) {
            float vx = sm[A_KT + kk * KTS + lane];
            float vy = sm[A_KT + kk * KTS + lane + 32];
            #pragma unroll
            for (int j = 0; j < 4; ++j) {
                float pp = sm[A_QSN + (wq + j) * SS + t * 64 + kk];
                acc[j].x += pp * vx;
                acc[j].y += pp * vy;
            }
        }
    }

    #pragma unroll
    for (int j = 0; j < 4; ++j) {
        size_t o = (size_t)(b * SS + q0 + wq + j) * HH + h * HD;
        store_split(&g_attnb0[o + lane],      &g_attnb1[o + lane],      acc[j].x * inv[j]);
        store_split(&g_attnb0[o + lane + 32], &g_attnb1[o + lane + 32], acc[j].y * inv[j]);
    }
}

// ---------------------------------------------------------------------------
// h1 = rmsnorm(x + attno): writes fp32 h1 AND bf16 hi/lo pair
// ---------------------------------------------------------------------------
__global__ void k_addrms(const float* __restrict__ x)
{
    __shared__ float ys[HH];
    __shared__ float red[256];
    const int r = blockIdx.x;
    float ss = 0.f;
    for (int i = threadIdx.x * 2; i < HH; i += 512) {
        float v0 = x[(size_t)r * HH + i]     + g_attno[(size_t)r * HH + i];
        float v1 = x[(size_t)r * HH + i + 1] + g_attno[(size_t)r * HH + i + 1];
        ys[i] = v0; ys[i + 1] = v1;
        ss += v0 * v0 + v1 * v1;
    }
    red[threadIdx.x] = ss;
    __syncthreads();
    for (int s = 128; s > 0; s >>= 1) {
        if (threadIdx.x < s) red[threadIdx.x] += red[threadIdx.x + s];
        __syncthreads();
    }
    float scale = rsqrtf(red[0] / (float)HH + EPSF);
    for (int i = threadIdx.x * 2; i < HH; i += 512) {
        float v0 = ys[i] * scale, v1 = ys[i + 1] * scale;
        *(float2*)&g_h1[(size_t)r * HH + i] = make_float2(v0, v1);
        *(uint32_t*)&g_h1b0[(size_t)r * HH + i] = hi_pack(v0, v1);
        *(uint32_t*)&g_h1b1[(size_t)r * HH + i] =
            pk_bf16x2(v0 - hi_of(v0), v1 - hi_of(v1));
    }
}

// ---------------------------------------------------------------------------
// SwiGLU activation: g_gu fp32 -> g_actb bf16 hi/lo
// ---------------------------------------------------------------------------
__global__ void k_act(int rows)
{
    const long long n = (long long)rows * (INTER / 2);
    for (long long p = (long long)blockIdx.x * blockDim.x + threadIdx.x;
         p < n; p += (long long)gridDim.x * blockDim.x) {
        long long r = p / (INTER / 2);
        int j = (int)(p % (INTER / 2)) * 2;
        const float* gp = &g_gu[r * GU + j];
        float g0 = gp[0], g1 = gp[1];
        float u0 = gp[INTER], u1 = gp[INTER + 1];
        float v0 = g0 / (1.f + expf(-g0)) * u0;
        float v1 = g1 / (1.f + expf(-g1)) * u1;
        *(uint32_t*)&g_actb0[r * INTER + j] = hi_pack(v0, v1);
        *(uint32_t*)&g_actb1[r * INTER + j] =
            pk_bf16x2(v0 - hi_of(v0), v1 - hi_of(v1));
    }
}

// ---------------------------------------------------------------------------
// Router: one warp per token.
// ---------------------------------------------------------------------------
__global__ void k_route(const float* __restrict__ Wr)
{
    __shared__ float xr[HH];
    __shared__ float logit_s[EE];
    __shared__ float probs[EE];
    const int t = blockIdx.x;
    const int lane = threadIdx.x;

    for (int i = lane; i < HH; i += 32) xr[i] = g_h1[(size_t)t * HH + i];
    __syncwarp();
    float acc = 0.f;
    for (int hh = 0; hh < HH; ++hh)
        acc = fmaf(xr[hh], Wr[(size_t)hh * EE + lane], acc);
    logit_s[lane] = acc;
    __syncwarp();

    if (lane == 0) {
        float m = -INFINITY;
        for (int e = 0; e < EE; ++e) m = fmaxf(m, logit_s[e]);
        float s = 0.f;
        for (int e = 0; e < EE; ++e) { float p = expf(logit_s[e] - m); probs[e] = p; s += p; }
        float inv = 1.f / s;
        for (int e = 0; e < EE; ++e) probs[e] *= inv;

        float dev[DD];
        for (int d = 0; d < DD; ++d)
            dev[d] = probs[4*d] + probs[4*d+1] + probs[4*d+2] + probs[4*d+3];
        bool devsel[DD];
        for (int d = 0; d < DD; ++d) devsel[d] = false;
        for (int rr = 0; rr < KDD; ++rr) {
            float best = -INFINITY; int bi = -1;
            for (int d = 0; d < DD; ++d)
                if (!devsel[d] && dev[d] > best) { best = dev[d]; bi = d; }
            devsel[bi] = true;
        }
        int idx6[KK]; float w6[KK];
        bool taken[EE];
        for (int e = 0; e < EE; ++e) taken[e] = false;
        for (int rr = 0; rr < KK; ++rr) {
            float best = -INFINITY; int bi = -1;
            for (int e = 0; e < EE; ++e)
                if (devsel[e >> 2] && !taken[e] && probs[e] > best) { best = probs[e]; bi = e; }
            taken[bi] = true; idx6[rr] = bi; w6[rr] = best;
        }
        float wm = -INFINITY;
        for (int rr = 0; rr < KK; ++rr) wm = fmaxf(wm, w6[rr]);
        float ws = 0.f;
        for (int rr = 0; rr < KK; ++rr) { w6[rr] = expf(w6[rr] - wm); ws += w6[rr]; }
        float winv = 1.f / ws;
        for (int rr = 0; rr < KK; ++rr) {
            w6[rr] *= winv;
            g_idx[t * KK + rr] = idx6[rr];
            g_w[t * KK + rr] = w6[rr];
            atomicAdd(&g_cnt[idx6[rr]], 1);
        }
        bool hit[DD];
        for (int d = 0; d < DD; ++d) hit[d] = false;
        for (int rr = 0; rr < KK; ++rr) hit[idx6[rr] >> 2] = true;
        for (int d = 0; d < DD; ++d)
            if (hit[d]) atomicAdd(&g_devhit[d], 1.0f);
    }
    __syncwarp();
    atomicAdd(&g_probsum[lane], probs[lane]);
}

__global__ void k_scan()
{
    int acc = 0;
    for (int e = 0; e < EE; ++e) {
        g_off[e] = acc;
        g_cur[e] = acc;
        acc += g_cnt[e];
    }
}

__global__ void k_build()
{
    int i = blockIdx.x * blockDim.x + threadIdx.x;
    if (i >= TOTSEL) return;
    int e = g_idx[i];
    int pos = atomicAdd(&g_cur[e], 1);
    g_tok[pos] = i / KK;
    g_wt[pos] = g_w[i];
}

// ---------------------------------------------------------------------------
// Final: out = rmsnorm(h1 + shared0 + shared1 + routed)  (+aux folded in)
// ---------------------------------------------------------------------------
__global__ void k_final(float* __restrict__ out, int do_aux)
{
    __shared__ float ys[HH];
    __shared__ float red[256];
    const int r = blockIdx.x;
    float ss = 0.f;
    for (int i = threadIdx.x; i < HH; i += 256) {
        size_t p = (size_t)r * HH + i;
        float v = g_h1[p] + g_shared[p] + g_shared[(size_t)TT * HH + p] + g_routed[p];
        ys[i] = v;
        ss += v * v;
    }
    red[threadIdx.x] = ss;
    __syncthreads();
    for (int s = 128; s > 0; s >>= 1) {
        if (threadIdx.x < s) red[threadIdx.x] += red[threadIdx.x + s];
        __syncthreads();
    }
    float scale = rsqrtf(red[0] / (float)HH + EPSF);
    for (int i = threadIdx.x; i < HH; i += 256)
        out[(size_t)r * HH + i] = ys[i] * scale;

    if (do_aux && r == 0 && threadIdx.x == 0) {
        float f_i[EE], P_i[EE];
        for (int e = 0; e < EE; ++e) {
            f_i[e] = (float)g_cnt[e] / ((float)TOTSEL + 1e-10f);
            P_i[e] = g_probsum[e] / (float)TT;
        }
        float eb = 0.f;
        for (int e = 0; e < EE; ++e) eb += f_i[e] * P_i[e];
        float expert_bal = fminf(eb * 0.003f, 10.f);
        float db = 0.f, cb = 0.f;
        for (int d = 0; d < DD; ++d) {
            float df = 0.f, dP = 0.f;
            for (int j = 0; j < EPD; ++j) { df += f_i[4*d + j]; dP += P_i[4*d + j]; }
            df *= 0.25f;
            db += df * dP;
            float fc = g_devhit[d] / ((float)(TT * KDD) + 1e-10f);
            cb += fc * dP;
        }
        out[(size_t)TT * HH] = expert_bal + fminf(db * 0.05f, 10.f) + fminf(cb * 0.02f, 10.f);
    }
}

// ---------------------------------------------------------------------------
// Launch
// ---------------------------------------------------------------------------
extern "C" void kernel_launch(void* const* d_in, const int* in_sizes, int n_in,
                              void* d_out, int out_size)
{
    const float* x     = (const float*)d_in[0];
    const float* Wqkv  = (const float*)d_in[1];
    const float* Wo    = (const float*)d_in[2];
    const float* Wgu_s = (const float*)d_in[3];
    const float* Wd_s  = (const float*)d_in[4];
    const float* Wr    = (const float*)d_in[5];
    const float* Wgu   = (const float*)d_in[6];
    const float* Wd    = (const float*)d_in[7];
    float* out = (float*)d_out;

    cudaFuncSetAttribute(k_attn2, cudaFuncAttributeMaxDynamicSharedMemorySize, ATT_SMEM);

    k_zero<<<(TT * HH + 255) / 256, 256>>>();
    k_cvt_x<<<512, 256>>>(x);

    // QKV: xb @ Wqkv -> g_qkv
    mma_gemm<0, false><<<dim3(24, 16, 1), 256>>>(AB_XB, BUF_QKV, Wqkv, 0, HH, 3 * HH, 0, 0);

    k_attn2<<<dim3(SS / AQB, NHH, BB), ATHR, ATT_SMEM>>>();

    // Wo: attnb @ Wo -> g_attno
    mma_gemm<0, false><<<dim3(8, 16, 1), 256>>>(AB_ATTNB, BUF_ATTNO, Wo, 0, HH, HH, 0, 0);

    k_addrms<<<TT, 256>>>(x);

    // Shared experts batched over z=2:
    // GU: h1b @ Wgu_s[z] -> g_gu rows [z*TT, z*TT+TT)
    mma_gemm<0, false><<<dim3(24, 16, 2), 256>>>(AB_H1B, BUF_GU, Wgu_s,
                                                 (long long)HH * GU, HH, GU, 0, TT);
    k_act<<<1024, 256>>>(2 * TT);
    // Down: actb rows [z*TT..] @ Wd_s[z] -> g_shared halves
    mma_gemm<0, false><<<dim3(8, 16, 2), 256>>>(AB_ACTB, BUF_SHARED, Wd_s,
                                                (long long)INTER * HH, INTER, HH, TT, TT);

    // Routing
    k_route<<<TT, 32>>>(Wr);
    k_scan<<<1, 1>>>();
    k_build<<<TOTSEL / 256, 256>>>();

    // Routed experts (grouped, gathered)
    mma_gemm<1, false><<<dim3(24, 16, EE), 256>>>(-1, -1, Wgu, (long long)HH * GU, HH, GU, 0, 0);
    k_act<<<2048, 256>>>(TOTSEL);
    mma_gemm<2, false><<<dim3(8, 16, EE), 256>>>(-1, -1, Wd, (long long)INTER * HH, INTER, HH, 0, 0);

    k_final<<<TT, 256>>>(out, out_size > TT * HH ? 1 : 0);
}